// round 16
// baseline (speedup 1.0000x reference)
#include <cuda_runtime.h>
#include <cstdint>
#include <cstddef>

#define NB 8
#define NPTS0 4096
#define NM0 2048
#define NM1 512
#define KNB 64
#define R0MAX (NB*NM0*KNB)   /* 1048576 */
#define R1MAX (NB*NM1*KNB)   /* 262144  */
#define EPSBN 1e-5f
#define CPC 512

// ----------------------------- device state -----------------------------
__device__ int    g_rowcnt[2];
__device__ int    g_done;                    // stats_fold ticket (always returns to 0)
__device__ double g_sum1[256], g_sq1[256];   // zero-init; re-zeroed by each fold
__device__ float  g_w2eff[128*128];
__device__ float  g_b2eff[128];
__device__ float  g_a2[256], g_c2[256];
__device__ int    g_ord0[NB*NPTS0];
__device__ int    g_ord1[NB*NM0];
__device__ float  g_pos1[NB*NM0*3];
__device__ float  g_pos2[NB*NM1*3];
__device__ int    g_rowCenter[R0MAX];
__device__ int    g_rowNbr[R0MAX];
__device__ int    g_cbase[NB*NM0];
__device__ int    g_ccnt[NB*NM0];
__device__ int    g_rowCenter1[R1MAX];
__device__ int    g_rowNbr1[R1MAX];
__device__ int    g_cbase1[NB*NM1];
__device__ int    g_ccnt1[NB*NM1];
__device__ float  g_x1[(size_t)NB*NM0*128];
__device__ float  g_featga[(size_t)NB*NM1*131];
__device__ float  g_bufA[(size_t)R0MAX*64];
__device__ float  g_bufB[(size_t)R0MAX*128];

// ----------------------------- helpers -----------------------------
__device__ __forceinline__ float d2rn(float ax,float ay,float az,float bx,float by,float bz){
  float dx=ax-bx, dy=ay-by, dz=az-bz;
  return __fadd_rn(__fadd_rn(__fmul_rn(dx,dx),__fmul_rn(dy,dy)),__fmul_rn(dz,dz));
}

// packed f32x2 ops: per-lane rounding identical to scalar __fadd_rn/__fmul_rn
__device__ __forceinline__ unsigned long long pk2(float lo,float hi){
  unsigned long long r; asm("mov.b64 %0,{%1,%2};":"=l"(r):"f"(lo),"f"(hi)); return r;
}
__device__ __forceinline__ void upk2(unsigned long long v,float& lo,float& hi){
  asm("mov.b64 {%0,%1},%2;":"=f"(lo),"=f"(hi):"l"(v));
}
__device__ __forceinline__ unsigned long long addx2(unsigned long long a,unsigned long long b){
  unsigned long long r; asm("add.rn.f32x2 %0,%1,%2;":"=l"(r):"l"(a),"l"(b)); return r;
}
__device__ __forceinline__ unsigned long long mulx2(unsigned long long a,unsigned long long b){
  unsigned long long r; asm("mul.rn.f32x2 %0,%1,%2;":"=l"(r):"l"(a),"l"(b)); return r;
}
__device__ __forceinline__ unsigned long long umax64(unsigned long long a,unsigned long long b){
  return a>b?a:b;
}

// ----------------------------- Morton counting sort (per batch) -----------------------------
__device__ __forceinline__ unsigned spread4(unsigned v){
  return (v&1u) | ((v&2u)<<2) | ((v&4u)<<4) | ((v&8u)<<6);
}
__device__ __forceinline__ int mcode(float x,float y,float z){
  int qx=min(15,max(0,(int)((x+4.f)*2.f)));
  int qy=min(15,max(0,(int)((y+4.f)*2.f)));
  int qz=min(15,max(0,(int)((z+4.f)*2.f)));
  return (int)(spread4(qx) | (spread4(qy)<<1) | (spread4(qz)<<2));
}

// also zeroes the row counter for its stage (block 0)
__global__ void sortpts(const float* __restrict__ pos,int Npts,int* __restrict__ order,int cidx){
  __shared__ int hist[4096];
  __shared__ int wtot[8];
  int b=blockIdx.x, tid=threadIdx.x, lane=tid&31, w=tid>>5;
  if(b==0&&tid==0) g_rowcnt[cidx]=0;
  const float* pb=pos+(size_t)b*Npts*3;
  for(int i=tid;i<4096;i+=256) hist[i]=0;
  __syncthreads();
  for(int j=tid;j<Npts;j+=256)
    atomicAdd(&hist[mcode(pb[j*3],pb[j*3+1],pb[j*3+2])],1);
  __syncthreads();
  int loc[16]; int s=0;
#pragma unroll
  for(int k=0;k<16;k++){ loc[k]=s; s+=hist[tid*16+k]; }
  int v=s;
#pragma unroll
  for(int off=1;off<32;off<<=1){
    int n=__shfl_up_sync(0xffffffffu,v,off);
    if(lane>=off) v+=n;
  }
  if(lane==31) wtot[w]=v;
  __syncthreads();
  if(tid==0){ int a=0; for(int k=0;k<8;k++){ int t2=wtot[k]; wtot[k]=a; a+=t2; } }
  __syncthreads();
  int excl=v-s+wtot[w];
#pragma unroll
  for(int k=0;k<16;k++) hist[tid*16+k]=excl+loc[k];
  __syncthreads();
  int* ob=order+(size_t)b*Npts;
  for(int j=tid;j<Npts;j+=256){
    int c=mcode(pb[j*3],pb[j*3+1],pb[j*3+2]);
    int p=atomicAdd(&hist[c],1);
    ob[p]=j;
  }
}

// ----------------------------- FPS v11: per-subregion (max,argmin-idx) caches -----------------------------
// Round-14 fps9 structure (contiguous regions, thr2 caches, float4 spos, tree
// slot scan) with the P-point index scan replaced by per-subregion
// (submax, subimin) caches: the sweep tracks argmax-with-min-pid inline (only
// swept subregions; non-swept caches stay valid since mind unchanged), and the
// lane candidate comes from a 3-op u64 tree on (value<<32)|~pid. Equivalence:
// min pid over all points with mind==vloc == min over subregions with
// submax==vloc of subimin == what the u64 max tree yields. Selections
// bit-identical to fps9.
template<int P>
__global__ void fps11(const float* __restrict__ pos,const int* __restrict__ order,
                      int Npts,int m,float* __restrict__ centers){
  constexpr int SUBP=P/4;
  constexpr int SUBN=8*P;              // 32*SUBP points per subregion
  extern __shared__ float sdyn[];      // [Npts*4] spos(float4) + [m] int wlist
  float* spos=sdyn;
  int* wlist=(int*)(sdyn+(size_t)Npts*4);
  __shared__ unsigned long long slot[2][8];
  int b=blockIdx.x, tid=threadIdx.x, lane=tid&31, w=tid>>5;
  const float* pb=pos+(size_t)b*Npts*3;
  for(int i=tid;i<Npts;i+=256){
    spos[i*4+0]=pb[i*3+0]; spos[i*4+1]=pb[i*3+1]; spos[i*4+2]=pb[i*3+2]; spos[i*4+3]=0.f;
  }
  __syncthreads();
  int region=((w&3)<<1)|(w>>2);
  int wbase=region*(P*32);
  const int* ob=order+(size_t)b*Npts;
  int pid[P]; float mind[P];
  unsigned long long px2[P/2],py2[P/2],pz2[P/2];
  float ctrx[4],ctry[4],ctrz[4],radr[4],submax[4],thr2[4];
  int subimin[4];
#pragma unroll
  for(int r=0;r<4;r++){
    float lx[SUBP],ly[SUBP],lz[SUBP];
    float sx=0.f,sy=0.f,sz=0.f;
#pragma unroll
    for(int e=0;e<SUBP;e++){
      int o=ob[wbase + r*SUBN + lane*SUBP + e];
      int p=r*SUBP+e; pid[p]=o;
      lx[e]=spos[o*4]; ly[e]=spos[o*4+1]; lz[e]=spos[o*4+2];
      sx+=lx[e]; sy+=ly[e]; sz+=lz[e];
      mind[p]=__int_as_float(0x7f800000);
    }
#pragma unroll
    for(int off=16;off;off>>=1){
      sx+=__shfl_down_sync(0xffffffffu,sx,off);
      sy+=__shfl_down_sync(0xffffffffu,sy,off);
      sz+=__shfl_down_sync(0xffffffffu,sz,off);
    }
    float cxr=__shfl_sync(0xffffffffu,sx,0)*(1.f/SUBN);
    float cyr=__shfl_sync(0xffffffffu,sy,0)*(1.f/SUBN);
    float czr=__shfl_sync(0xffffffffu,sz,0)*(1.f/SUBN);
    float md2=0.f;
#pragma unroll
    for(int e=0;e<SUBP;e++){
      float dx=lx[e]-cxr,dy=ly[e]-cyr,dz=lz[e]-czr;
      md2=fmaxf(md2,fmaf(dx,dx,fmaf(dy,dy,dz*dz)));
    }
    md2=__uint_as_float(__reduce_max_sync(0xffffffffu,__float_as_uint(md2)));
    ctrx[r]=cxr; ctry[r]=cyr; ctrz[r]=czr;
    radr[r]=sqrtf(md2)+1e-4f;
    submax[r]=__int_as_float(0x7f800000);
    subimin[r]=0x7fffffff;
    thr2[r]=__int_as_float(0x7f800000);           // +inf -> first iteration fully active
#pragma unroll
    for(int j=0;j<SUBP/2;j++){
      px2[r*(SUBP/2)+j]=pk2(lx[2*j],lx[2*j+1]);
      py2[r*(SUBP/2)+j]=pk2(ly[2*j],ly[2*j+1]);
      pz2[r*(SUBP/2)+j]=pk2(lz[2*j],lz[2*j+1]);
    }
  }
  float cx=spos[0],cy=spos[1],cz=spos[2];
  unsigned wvmax=0x7f800000u;          // cached warp max (bits)
  int wimin=0;
  if(tid==0) wlist[0]=0;
  for(int i=1;i<m;i++){
    bool act[4]; bool any=false;
#pragma unroll
    for(int r=0;r<4;r++){
      float dgx=cx-ctrx[r],dgy=cy-ctry[r],dgz=cz-ctrz[r];
      float d2g=fmaf(dgx,dgx,fmaf(dgy,dgy,dgz*dgz));
      act[r]=(d2g<thr2[r]);
      any|=act[r];
    }
    if(any){                                      // warp-uniform (sphere data lane-identical)
      unsigned long long ncx=pk2(-cx,-cx),ncy=pk2(-cy,-cy),ncz=pk2(-cz,-cz);
#pragma unroll
      for(int r=0;r<4;r++) if(act[r]){
        float mr=-1.f; int mi=0x7fffffff;
#pragma unroll
        for(int j=0;j<SUBP/2;j++){
          int p2=r*(SUBP/2)+j, p=r*SUBP+2*j;
          unsigned long long dx=addx2(px2[p2],ncx);
          unsigned long long dy=addx2(py2[p2],ncy);
          unsigned long long dz=addx2(pz2[p2],ncz);
          unsigned long long sx=mulx2(dx,dx);
          unsigned long long sy=mulx2(dy,dy);
          unsigned long long sz=mulx2(dz,dz);
          unsigned long long d2=addx2(addx2(sx,sy),sz);
          float dlo,dhi; upk2(d2,dlo,dhi);
          float m0=fminf(mind[p],dlo);   mind[p]=m0;
          float m1=fminf(mind[p+1],dhi); mind[p+1]=m1;
          if(m0>mr||(m0==mr&&pid[p]<mi)){mr=m0;mi=pid[p];}
          if(m1>mr||(m1==mr&&pid[p+1]<mi)){mr=m1;mi=pid[p+1];}
        }
        submax[r]=mr; subimin[r]=mi;
      }
      // lane candidate via u64 tree: (value bits << 32) | ~pid -> max value, min pid
      unsigned long long e0=((unsigned long long)__float_as_uint(submax[0])<<32)|(unsigned)(~subimin[0]);
      unsigned long long e1=((unsigned long long)__float_as_uint(submax[1])<<32)|(unsigned)(~subimin[1]);
      unsigned long long e2=((unsigned long long)__float_as_uint(submax[2])<<32)|(unsigned)(~subimin[2]);
      unsigned long long e3=((unsigned long long)__float_as_uint(submax[3])<<32)|(unsigned)(~subimin[3]);
      unsigned long long eb=umax64(umax64(e0,e1),umax64(e2,e3));
      unsigned fb=(unsigned)(eb>>32);
      int cpid=(int)(~(unsigned)eb);
      unsigned vm=__reduce_max_sync(0xffffffffu,fb);
      unsigned cand=(fb==vm)? (unsigned)cpid : 0xffffffffu;
      unsigned im=__reduce_min_sync(0xffffffffu,cand);
      wvmax=vm; wimin=(int)im;
      float sth=sqrtf(__uint_as_float(vm));
#pragma unroll
      for(int r=0;r<4;r++){ float t=radr[r]+1e-3f+sth; thr2[r]=t*t; }
    }
    int par=i&1;
    if(lane==0) slot[par][w]=((unsigned long long)wvmax<<32)|(unsigned)(~wimin);
    __syncthreads();
    unsigned long long s0=slot[par][0],s1=slot[par][1],s2=slot[par][2],s3=slot[par][3];
    unsigned long long s4=slot[par][4],s5=slot[par][5],s6=slot[par][6],s7=slot[par][7];
    s0=umax64(s0,s1); s2=umax64(s2,s3); s4=umax64(s4,s5); s6=umax64(s6,s7);
    s0=umax64(s0,s2); s4=umax64(s4,s6);
    unsigned long long best=umax64(s0,s4);
    int wpid=(int)(~((unsigned)best));
    if(tid==0) wlist[i]=wpid;
    float4 wc=*(const float4*)(spos+(size_t)wpid*4);
    cx=wc.x; cy=wc.y; cz=wc.z;
  }
  __syncthreads();
  float* dst=centers+(size_t)b*m*3;
  for(int i=tid;i<m;i+=256){
    int p=wlist[i];
    dst[i*3]=spos[p*4]; dst[i*3+1]=spos[p*4+1]; dst[i*3+2]=spos[p*4+2];
  }
}

// ------------------- radius neighbors, 8 centers/block, packed f32x2 -------------------
__global__ void nbr8(const float* __restrict__ pos,int Npts,
                     const float* __restrict__ cen,int m,float r2,int cidx,
                     int* __restrict__ rowC,int* __restrict__ rowN,
                     int* __restrict__ cbase,int* __restrict__ ccnt){
  __shared__ float cd[8][CPC]; __shared__ int ci[8][CPC];
  __shared__ int scnt[8];
  __shared__ float cc[24];
  int b=blockIdx.y, tid=threadIdx.x, lane=tid&31, w=tid>>5;
  int c0=blockIdx.x*8;
  if(tid<8) scnt[tid]=0;
  if(tid<24) cc[tid]=cen[((size_t)(b*m+c0))*3+tid];
  __syncthreads();
  unsigned long long pcx[4],pcy[4],pcz[4];
#pragma unroll
  for(int kp=0;kp<4;kp++){
    pcx[kp]=pk2(cc[(2*kp)*3],  cc[(2*kp+1)*3]);
    pcy[kp]=pk2(cc[(2*kp)*3+1],cc[(2*kp+1)*3+1]);
    pcz[kp]=pk2(cc[(2*kp)*3+2],cc[(2*kp+1)*3+2]);
  }
  const float* pb=pos+(size_t)b*Npts*3;
  for(int j=tid;j<Npts;j+=256){
    float x=pb[j*3],y=pb[j*3+1],z=pb[j*3+2];
    unsigned long long nx=pk2(-x,-x),ny=pk2(-y,-y),nz=pk2(-z,-z);
#pragma unroll
    for(int kp=0;kp<4;kp++){
      unsigned long long dx=addx2(pcx[kp],nx);
      unsigned long long dy=addx2(pcy[kp],ny);
      unsigned long long dz=addx2(pcz[kp],nz);
      unsigned long long sx=mulx2(dx,dx);
      unsigned long long sy=mulx2(dy,dy);
      unsigned long long sz=mulx2(dz,dz);
      unsigned long long d2=addx2(addx2(sx,sy),sz);
      float d0,d1; upk2(d2,d0,d1);
      if(d0<=r2){
        int p=atomicAdd(&scnt[2*kp],1);
        if(p<CPC){ cd[2*kp][p]=d0; ci[2*kp][p]=j; }
      }
      if(d1<=r2){
        int p=atomicAdd(&scnt[2*kp+1],1);
        if(p<CPC){ cd[2*kp+1][p]=d1; ci[2*kp+1][p]=j; }
      }
    }
  }
  __syncthreads();
  int gc=b*m+c0+w;
  int n=scnt[w];
  int cnt=min(n,KNB);
  int basev=0;
  if(lane==0) basev=atomicAdd(&g_rowcnt[cidx],cnt);
  basev=__shfl_sync(0xffffffffu,basev,0);
  if(lane==0){ cbase[gc]=basev; ccnt[gc]=cnt; }
  if(n<=KNB){
    for(int q=lane;q<cnt;q+=32){
      rowC[basev+q]=gc;
      rowN[basev+q]=ci[w][q];
    }
  }else{
    int nn=min(n,CPC);
    for(int s=0;s<KNB;s++){
      float bvv=__int_as_float(0x7f800000); int bid=0x7fffffff; int bp=-1;
      for(int p=lane;p<nn;p+=32){
        float v=cd[w][p]; int id=ci[w][p];
        if(v<bvv||(v==bvv&&id<bid)){bvv=v;bid=id;bp=p;}
      }
#pragma unroll
      for(int off=16;off;off>>=1){
        float ov=__shfl_down_sync(0xffffffffu,bvv,off);
        int   oi=__shfl_down_sync(0xffffffffu,bid,off);
        int   op=__shfl_down_sync(0xffffffffu,bp,off);
        if(ov<bvv||(ov==bvv&&oi<bid)){bvv=ov;bid=oi;bp=op;}
      }
      bp=__shfl_sync(0xffffffffu,bp,0);
      if(lane==0){ rowC[basev+s]=gc; rowN[basev+s]=bid; }
      if(lane==0) cd[w][bp]=__int_as_float(0x7f800000);
      __syncwarp();
    }
  }
}

// ------------------- SA0 layer1: rel(3) -> 64, relu -------------------
__global__ void pass1_sa0(const float* __restrict__ pos,
                          const float* __restrict__ w1,const float* __restrict__ b1){
  __shared__ float sw[3*64]; __shared__ float sb[64];
  int R=g_rowcnt[0];
  if(blockIdx.x*256>=R) return;
  int tid=threadIdx.x;
  if(tid<192) sw[tid]=w1[tid];
  if(tid<64)  sb[tid]=b1[tid];
  __syncthreads();
  int r=blockIdx.x*256+tid;
  if(r>=R) return;
  int gc=g_rowCenter[r], j=g_rowNbr[r];
  int b=gc/NM0;
  const float* pj=pos+((size_t)b*NPTS0+j)*3;
  float r0=pj[0]-g_pos1[gc*3], r1=pj[1]-g_pos1[gc*3+1], r2=pj[2]-g_pos1[gc*3+2];
  float4* out=(float4*)(g_bufA+(size_t)r*64);
#pragma unroll
  for(int q=0;q<16;q++){
    float4 v;
    v.x=fmaxf(fmaf(r0,sw[q*4+0],fmaf(r1,sw[64+q*4+0],fmaf(r2,sw[128+q*4+0],sb[q*4+0]))),0.f);
    v.y=fmaxf(fmaf(r0,sw[q*4+1],fmaf(r1,sw[64+q*4+1],fmaf(r2,sw[128+q*4+1],sb[q*4+1]))),0.f);
    v.z=fmaxf(fmaf(r0,sw[q*4+2],fmaf(r1,sw[64+q*4+2],fmaf(r2,sw[128+q*4+2],sb[q*4+2]))),0.f);
    v.w=fmaxf(fmaf(r0,sw[q*4+3],fmaf(r1,sw[64+q*4+3],fmaf(r2,sw[128+q*4+3],sb[q*4+3]))),0.f);
    out[q]=v;
  }
}

// ------------- fused masked BN stats + fold (last-block pattern) -------------
__global__ void stats_fold(int sel,int C,int Rparam,int cidx,int mode,
                           const float* __restrict__ gma,const float* __restrict__ bet,
                           const float* __restrict__ w2,const float* __restrict__ b2){
  __shared__ float ssm[256], sqm[256];
  __shared__ bool isLast;
  int tid=threadIdx.x;
  int R=(Rparam>=0)? Rparam : g_rowcnt[cidx];
  const float* buf = sel ? g_bufB : g_bufA;
  int t=blockIdx.x*256+tid;
  int ch=t%C;
  int rstep=(gridDim.x*256)/C;
  float s0=0.f,q0=0.f,s1=0.f,q1=0.f;
  int r=t/C;
  for(; r+rstep<R; r+=2*rstep){
    float v0=buf[(size_t)r*C+ch];
    float v1=buf[(size_t)(r+rstep)*C+ch];
    s0+=v0; q0=fmaf(v0,v0,q0);
    s1+=v1; q1=fmaf(v1,v1,q1);
  }
  if(r<R){ float v=buf[(size_t)r*C+ch]; s0+=v; q0=fmaf(v,v,q0); }
  ssm[tid]=s0+s1; sqm[tid]=q0+q1;
  __syncthreads();
  for(int step=128; step>=C; step>>=1){
    if(tid<step){ ssm[tid]+=ssm[tid+step]; sqm[tid]+=sqm[tid+step]; }
    __syncthreads();
  }
  if(tid<C){
    atomicAdd(&g_sum1[tid],(double)ssm[tid]);
    atomicAdd(&g_sq1[tid],(double)sqm[tid]);
  }
  __threadfence();
  __syncthreads();
  if(tid==0) isLast=(atomicAdd(&g_done,1)==(int)gridDim.x-1);
  __syncthreads();
  if(!isLast) return;
  __shared__ float a1[256], c1[256];
  double cnt=(double)R;
  if(tid<C){
    double mu=g_sum1[tid]/cnt;
    double var=g_sq1[tid]/cnt-mu*mu;
    float a=gma[tid]*rsqrtf((float)var+EPSBN);
    a1[tid]=a; c1[tid]=bet[tid]-a*(float)mu;
    g_sum1[tid]=0.0; g_sq1[tid]=0.0;
  }
  __syncthreads();
  if(mode==0){
    for(int i=tid;i<C*128;i+=256) g_w2eff[i]=a1[i>>7]*w2[i];
    if(tid<128){
      float s=b2[tid];
      for(int k=0;k<C;k++) s=fmaf(c1[k],w2[k*128+tid],s);
      g_b2eff[tid]=s;
    }
  }else{
    if(tid<C){ g_a2[tid]=a1[tid]; g_c2[tid]=c1[tid]; }
  }
  if(tid==0) g_done=0;
}

// ------------------- layer2 tiled GEMM -------------------
__global__ void pass2(int C1,int cidx){
  int R=g_rowcnt[cidx];
  int r0=blockIdx.x*64;
  if(r0>=R) return;
  __shared__ __align__(16) float Ws[32*128];
  __shared__ __align__(16) float As[64*32];
  int tid=threadIdx.x;
  int row=tid>>2, cg=tid&3;
  float acc[32];
#pragma unroll
  for(int j=0;j<32;j++) acc[j]=g_b2eff[cg*32+j];
  int nchunks=C1>>5;
  for(int kc=0;kc<nchunks;kc++){
    for(int i=tid;i<4096;i+=256) Ws[i]=g_w2eff[kc*4096+i];
    for(int i=tid;i<2048;i+=256){
      int rr=i>>5, kk=i&31; int rA=r0+rr;
      As[i]=(rA<R)? g_bufA[(size_t)rA*C1+kc*32+kk] : 0.f;
    }
    __syncthreads();
#pragma unroll 8
    for(int kk=0;kk<32;kk++){
      float a=As[row*32+kk];
      const float4* w4=(const float4*)(Ws+kk*128+cg*32);
#pragma unroll
      for(int j=0;j<8;j++){
        float4 w=w4[j];
        acc[j*4+0]=fmaf(a,w.x,acc[j*4+0]);
        acc[j*4+1]=fmaf(a,w.y,acc[j*4+1]);
        acc[j*4+2]=fmaf(a,w.z,acc[j*4+2]);
        acc[j*4+3]=fmaf(a,w.w,acc[j*4+3]);
      }
    }
    __syncthreads();
  }
  int rA=r0+row;
  if(rA<R){
    float* out=g_bufB+(size_t)rA*128+cg*32;
#pragma unroll
    for(int j=0;j<32;j++) out[j]=fmaxf(acc[j],0.f);
  }
}

// ------------------- SA1 layer1 -------------------
__global__ void pass1_sa1(const float* __restrict__ w1,const float* __restrict__ b1){
  int R=g_rowcnt[1];
  int r0=blockIdx.x*64;
  if(r0>=R) return;
  __shared__ __align__(16) float Ws[32*128];
  __shared__ __align__(16) float As[64*32];
  __shared__ int xrow[64]; __shared__ int gcl[64];
  int tid=threadIdx.x;
  if(tid<64){
    int rA=r0+tid;
    int gc=(rA<R)? g_rowCenter1[rA]:0;
    int j =(rA<R)? g_rowNbr1[rA]:0;
    gcl[tid]=gc; xrow[tid]=(gc>>9)*NM0 + j;
  }
  __syncthreads();
  int row=tid>>2, cg=tid&3;
  float acc[32];
#pragma unroll
  for(int j=0;j<32;j++) acc[j]=b1[cg*32+j];
  for(int kc=0;kc<5;kc++){
    for(int i=tid;i<4096;i+=256){
      int kk=i>>7, ch=i&127; int kg=kc*32+kk;
      Ws[i]=(kg<131)? w1[kg*128+ch] : 0.f;
    }
    for(int i=tid;i<2048;i+=256){
      int rr=i>>5, kk=i&31; int rA=r0+rr;
      float v=0.f;
      if(rA<R){
        if(kc<4)       v=g_x1[(size_t)xrow[rr]*128+kc*32+kk];
        else if(kk<3)  v=g_pos1[xrow[rr]*3+kk]-g_pos2[gcl[rr]*3+kk];
      }
      As[i]=v;
    }
    __syncthreads();
#pragma unroll 8
    for(int kk=0;kk<32;kk++){
      float a=As[row*32+kk];
      const float4* w4=(const float4*)(Ws+kk*128+cg*32);
#pragma unroll
      for(int j=0;j<8;j++){
        float4 w=w4[j];
        acc[j*4+0]=fmaf(a,w.x,acc[j*4+0]);
        acc[j*4+1]=fmaf(a,w.y,acc[j*4+1]);
        acc[j*4+2]=fmaf(a,w.z,acc[j*4+2]);
        acc[j*4+3]=fmaf(a,w.w,acc[j*4+3]);
      }
    }
    __syncthreads();
  }
  int rA=r0+row;
  if(rA<R){
    float* out=g_bufA+(size_t)rA*128+cg*32;
#pragma unroll
    for(int j=0;j<32;j++) out[j]=fmaxf(acc[j],0.f);
  }
}

// ------------------- per-center max + BN2 affine -------------------
__global__ void maxfin_sa0(){
  int gc=blockIdx.x, ch=threadIdx.x;
  int base=g_cbase[gc], cnt=g_ccnt[gc];
  float mx=__int_as_float(0xff800000);
  for(int k=0;k<cnt;k++) mx=fmaxf(mx,g_bufB[(size_t)(base+k)*128+ch]);
  g_x1[(size_t)gc*128+ch]=fmaf(g_a2[ch],mx,g_c2[ch]);
}

__global__ void maxfin_sa1(){
  int gc=blockIdx.x, ch=threadIdx.x;
  int base=g_cbase1[gc], cnt=g_ccnt1[gc];
  float mx=__int_as_float(0xff800000);
  for(int k=0;k<cnt;k++) mx=fmaxf(mx,g_bufB[(size_t)(base+k)*128+ch]);
  g_featga[(size_t)gc*131+ch]=fmaf(g_a2[ch],mx,g_c2[ch]);
  if(ch<3) g_featga[(size_t)gc*131+128+ch]=g_pos2[gc*3+ch];
}

// ------------------- global MLP -------------------
__global__ void ga_pass(const float* __restrict__ w,const float* __restrict__ bias){
  __shared__ __align__(16) float Ws[32*256];
  __shared__ __align__(16) float As[32*32];
  int tid=threadIdx.x;
  int r0=blockIdx.x*32;
  int row=tid>>3, cg=tid&7; int ch0=cg*32;
  float acc[32];
#pragma unroll
  for(int j=0;j<32;j++) acc[j]=bias[ch0+j];
  for(int kc=0;kc<5;kc++){
    for(int i=tid;i<8192;i+=256){
      int kk=i>>8, ch=i&255; int kg=kc*32+kk;
      Ws[i]=(kg<131)? w[kg*256+ch] : 0.f;
    }
    for(int i=tid;i<1024;i+=256){
      int rr=i>>5, kk=i&31; int kg=kc*32+kk;
      As[i]=(kg<131)? g_featga[(size_t)(r0+rr)*131+kg] : 0.f;
    }
    __syncthreads();
#pragma unroll 8
    for(int kk=0;kk<32;kk++){
      float a=As[row*32+kk];
      const float4* w4=(const float4*)(Ws+kk*256+ch0);
#pragma unroll
      for(int j=0;j<8;j++){
        float4 wv=w4[j];
        acc[j*4+0]=fmaf(a,wv.x,acc[j*4+0]);
        acc[j*4+1]=fmaf(a,wv.y,acc[j*4+1]);
        acc[j*4+2]=fmaf(a,wv.z,acc[j*4+2]);
        acc[j*4+3]=fmaf(a,wv.w,acc[j*4+3]);
      }
    }
    __syncthreads();
  }
  float* out=g_bufB+(size_t)(r0+row)*256+ch0;
#pragma unroll
  for(int j=0;j<32;j++) out[j]=fmaxf(acc[j],0.f);
}

// ------------------- global max + BN + FC head -------------------
__global__ void final_kernel(const float* __restrict__ l0w,const float* __restrict__ l0b,
                             const float* __restrict__ l1w,const float* __restrict__ l1b,
                             float* __restrict__ out){
  __shared__ float sy[256], sz[256];
  int b=blockIdx.x, ch=threadIdx.x;
  const float* bb=g_bufB+(size_t)b*512*256;
  float m0=__int_as_float(0xff800000), m1=m0, m2=m0, m3=m0;
  for(int r=0;r<512;r+=4){
    m0=fmaxf(m0,bb[(r+0)*256+ch]);
    m1=fmaxf(m1,bb[(r+1)*256+ch]);
    m2=fmaxf(m2,bb[(r+2)*256+ch]);
    m3=fmaxf(m3,bb[(r+3)*256+ch]);
  }
  float mx=fmaxf(fmaxf(m0,m1),fmaxf(m2,m3));
  sy[ch]=fmaxf(fmaf(g_a2[ch],mx,g_c2[ch]),0.f);
  __syncthreads();
  float s=l0b[ch];
  for(int k=0;k<256;k++) s=fmaf(sy[k],l0w[k*256+ch],s);
  sz[ch]=fmaxf(s,0.f);
  __syncthreads();
  if(ch<10){
    float o=l1b[ch];
    for(int k=0;k<256;k++) o=fmaf(sz[k],l1w[k*10+ch],o);
    out[b*10+ch]=o;
  }
}

// ----------------------------- host launch -----------------------------
extern "C" void kernel_launch(void* const* d_in, const int* in_sizes, int n_in,
                              void* d_out, int out_size){
  const float* pos    =(const float*)d_in[0];
  const float* sa0_w1 =(const float*)d_in[1];
  const float* sa0_b1 =(const float*)d_in[2];
  const float* sa0_g1 =(const float*)d_in[3];
  const float* sa0_be1=(const float*)d_in[4];
  const float* sa0_w2 =(const float*)d_in[5];
  const float* sa0_b2 =(const float*)d_in[6];
  const float* sa0_g2 =(const float*)d_in[7];
  const float* sa0_be2=(const float*)d_in[8];
  const float* sa1_w1 =(const float*)d_in[9];
  const float* sa1_b1 =(const float*)d_in[10];
  const float* sa1_g1 =(const float*)d_in[11];
  const float* sa1_be1=(const float*)d_in[12];
  const float* sa1_w2 =(const float*)d_in[13];
  const float* sa1_b2 =(const float*)d_in[14];
  const float* sa1_g2 =(const float*)d_in[15];
  const float* sa1_be2=(const float*)d_in[16];
  const float* ga_w   =(const float*)d_in[17];
  const float* ga_b   =(const float*)d_in[18];
  const float* ga_g   =(const float*)d_in[19];
  const float* ga_be  =(const float*)d_in[20];
  const float* l0_w   =(const float*)d_in[21];
  const float* l0_b   =(const float*)d_in[22];
  const float* l1_w   =(const float*)d_in[23];
  const float* l1_b   =(const float*)d_in[24];
  float* out=(float*)d_out;

  void *p_pos1,*p_pos2,*p_ord0,*p_ord1;
  void *p_rc0,*p_rn0,*p_cb0,*p_cc0,*p_rc1,*p_rn1,*p_cb1,*p_cc1;
  cudaGetSymbolAddress(&p_pos1,g_pos1);
  cudaGetSymbolAddress(&p_pos2,g_pos2);
  cudaGetSymbolAddress(&p_ord0,g_ord0);
  cudaGetSymbolAddress(&p_ord1,g_ord1);
  cudaGetSymbolAddress(&p_rc0,g_rowCenter);
  cudaGetSymbolAddress(&p_rn0,g_rowNbr);
  cudaGetSymbolAddress(&p_cb0,g_cbase);
  cudaGetSymbolAddress(&p_cc0,g_ccnt);
  cudaGetSymbolAddress(&p_rc1,g_rowCenter1);
  cudaGetSymbolAddress(&p_rn1,g_rowNbr1);
  cudaGetSymbolAddress(&p_cb1,g_cbase1);
  cudaGetSymbolAddress(&p_cc1,g_ccnt1);

  static cudaStream_t s1=nullptr;
  static cudaEvent_t e0=nullptr,e1=nullptr;
  if(!s1){
    cudaStreamCreateWithFlags(&s1,cudaStreamNonBlocking);
    cudaEventCreateWithFlags(&e0,cudaEventDisableTiming);
    cudaEventCreateWithFlags(&e1,cudaEventDisableTiming);
  }

  const int SM0=(NPTS0*4+NM0)*(int)sizeof(float);   // 73728 B
  const int SM1=(NM0*4+NM1)*(int)sizeof(float);     // 34816 B
  cudaFuncSetAttribute(fps11<16>,cudaFuncAttributeMaxDynamicSharedMemorySize,SM0);
  cudaFuncSetAttribute(fps11<8>, cudaFuncAttributeMaxDynamicSharedMemorySize,SM1);

  const float R2_0=(float)(0.2*0.2);
  const float R2_1=(float)(0.4*0.4);

  // ---------------- SA0 geometry (stream 0) ----------------
  sortpts<<<NB,256>>>(pos,NPTS0,(int*)p_ord0,0);
  fps11<16><<<NB,256,SM0>>>(pos,(const int*)p_ord0,NPTS0,NM0,(float*)p_pos1);
  cudaEventRecord(e0,0);

  // ---------------- SA1 geometry (stream s1, depends only on pos1) ----------------
  cudaStreamWaitEvent(s1,e0,0);
  sortpts<<<NB,256,0,s1>>>((const float*)p_pos1,NM0,(int*)p_ord1,1);
  fps11<8><<<NB,256,SM1,s1>>>((const float*)p_pos1,(const int*)p_ord1,NM0,NM1,(float*)p_pos2);
  { dim3 g(NM1/8,NB);
    nbr8<<<g,256,0,s1>>>((const float*)p_pos1,NM0,(const float*)p_pos2,NM1,R2_1,1,
                         (int*)p_rc1,(int*)p_rn1,(int*)p_cb1,(int*)p_cc1); }
  cudaEventRecord(e1,s1);

  // ---------------- SA0 MLP chain (stream 0, concurrent with s1) ----------------
  { dim3 g(NM0/8,NB);
    nbr8<<<g,256>>>(pos,NPTS0,(const float*)p_pos1,NM0,R2_0,0,
                    (int*)p_rc0,(int*)p_rn0,(int*)p_cb0,(int*)p_cc0); }
  pass1_sa0<<<R0MAX/256,256>>>(pos,sa0_w1,sa0_b1);
  stats_fold<<<256,256>>>(0,64,-1,0,0,sa0_g1,sa0_be1,sa0_w2,sa0_b2);
  pass2<<<R0MAX/64,256>>>(64,0);
  stats_fold<<<256,256>>>(1,128,-1,0,1,sa0_g2,sa0_be2,nullptr,nullptr);
  maxfin_sa0<<<NB*NM0,128>>>();

  // ---------------- join, SA1 MLP chain ----------------
  cudaStreamWaitEvent(0,e1,0);
  pass1_sa1<<<R1MAX/64,256>>>(sa1_w1,sa1_b1);
  stats_fold<<<256,256>>>(0,128,-1,1,0,sa1_g1,sa1_be1,sa1_w2,sa1_b2);
  pass2<<<R1MAX/64,256>>>(128,1);
  stats_fold<<<256,256>>>(1,128,-1,1,1,sa1_g2,sa1_be2,nullptr,nullptr);
  maxfin_sa1<<<NB*NM1,128>>>();

  // ---------------- global MLP + head ----------------
  ga_pass<<<(NB*NM1)/32,256>>>(ga_w,ga_b);
  stats_fold<<<256,256>>>(1,256,NB*NM1,0,1,ga_g,ga_be,nullptr,nullptr);
  final_kernel<<<NB,256>>>(l0_w,l0_b,l1_w,l1_b,out);
}

// round 17
// speedup vs baseline: 1.2545x; 1.2545x over previous
#include <cuda_runtime.h>
#include <cstdint>
#include <cstddef>

#define NB 8
#define NPTS0 4096
#define NM0 2048
#define NM1 512
#define KNB 64
#define R0MAX (NB*NM0*KNB)   /* 1048576 */
#define R1MAX (NB*NM1*KNB)   /* 262144  */
#define EPSBN 1e-5f
#define CPC 512

// ----------------------------- device state -----------------------------
__device__ int    g_rowcnt[2];
__device__ int    g_done;                    // stats_fold ticket (always returns to 0)
__device__ double g_sum1[256], g_sq1[256];   // zero-init; re-zeroed by each fold
__device__ float  g_w2eff[128*128];
__device__ float  g_b2eff[128];
__device__ float  g_a2[256], g_c2[256];
__device__ int    g_ord0[NB*NPTS0];
__device__ int    g_ord1[NB*NM0];
__device__ float  g_pos1[NB*NM0*3];
__device__ float  g_pos2[NB*NM1*3];
__device__ int    g_rowCenter[R0MAX];
__device__ int    g_rowNbr[R0MAX];
__device__ int    g_cbase[NB*NM0];
__device__ int    g_ccnt[NB*NM0];
__device__ int    g_rowCenter1[R1MAX];
__device__ int    g_rowNbr1[R1MAX];
__device__ int    g_cbase1[NB*NM1];
__device__ int    g_ccnt1[NB*NM1];
__device__ float  g_x1[(size_t)NB*NM0*128];
__device__ float  g_featga[(size_t)NB*NM1*131];
__device__ float  g_bufA[(size_t)R0MAX*64];
__device__ float  g_bufB[(size_t)R0MAX*128];

// ----------------------------- helpers -----------------------------
__device__ __forceinline__ float d2rn(float ax,float ay,float az,float bx,float by,float bz){
  float dx=ax-bx, dy=ay-by, dz=az-bz;
  return __fadd_rn(__fadd_rn(__fmul_rn(dx,dx),__fmul_rn(dy,dy)),__fmul_rn(dz,dz));
}

// packed f32x2 ops: per-lane rounding identical to scalar __fadd_rn/__fmul_rn
__device__ __forceinline__ unsigned long long pk2(float lo,float hi){
  unsigned long long r; asm("mov.b64 %0,{%1,%2};":"=l"(r):"f"(lo),"f"(hi)); return r;
}
__device__ __forceinline__ void upk2(unsigned long long v,float& lo,float& hi){
  asm("mov.b64 {%0,%1},%2;":"=f"(lo),"=f"(hi):"l"(v));
}
__device__ __forceinline__ unsigned long long addx2(unsigned long long a,unsigned long long b){
  unsigned long long r; asm("add.rn.f32x2 %0,%1,%2;":"=l"(r):"l"(a),"l"(b)); return r;
}
__device__ __forceinline__ unsigned long long mulx2(unsigned long long a,unsigned long long b){
  unsigned long long r; asm("mul.rn.f32x2 %0,%1,%2;":"=l"(r):"l"(a),"l"(b)); return r;
}
__device__ __forceinline__ unsigned long long umax64(unsigned long long a,unsigned long long b){
  return a>b?a:b;
}

// ----------------------------- Morton counting sort (per batch) -----------------------------
__device__ __forceinline__ unsigned spread4(unsigned v){
  return (v&1u) | ((v&2u)<<2) | ((v&4u)<<4) | ((v&8u)<<6);
}
__device__ __forceinline__ int mcode(float x,float y,float z){
  int qx=min(15,max(0,(int)((x+4.f)*2.f)));
  int qy=min(15,max(0,(int)((y+4.f)*2.f)));
  int qz=min(15,max(0,(int)((z+4.f)*2.f)));
  return (int)(spread4(qx) | (spread4(qy)<<1) | (spread4(qz)<<2));
}

// also zeroes the row counter for its stage (block 0)
__global__ void sortpts(const float* __restrict__ pos,int Npts,int* __restrict__ order,int cidx){
  __shared__ int hist[4096];
  __shared__ int wtot[8];
  int b=blockIdx.x, tid=threadIdx.x, lane=tid&31, w=tid>>5;
  if(b==0&&tid==0) g_rowcnt[cidx]=0;
  const float* pb=pos+(size_t)b*Npts*3;
  for(int i=tid;i<4096;i+=256) hist[i]=0;
  __syncthreads();
  for(int j=tid;j<Npts;j+=256)
    atomicAdd(&hist[mcode(pb[j*3],pb[j*3+1],pb[j*3+2])],1);
  __syncthreads();
  int loc[16]; int s=0;
#pragma unroll
  for(int k=0;k<16;k++){ loc[k]=s; s+=hist[tid*16+k]; }
  int v=s;
#pragma unroll
  for(int off=1;off<32;off<<=1){
    int n=__shfl_up_sync(0xffffffffu,v,off);
    if(lane>=off) v+=n;
  }
  if(lane==31) wtot[w]=v;
  __syncthreads();
  if(tid==0){ int a=0; for(int k=0;k<8;k++){ int t2=wtot[k]; wtot[k]=a; a+=t2; } }
  __syncthreads();
  int excl=v-s+wtot[w];
#pragma unroll
  for(int k=0;k<16;k++) hist[tid*16+k]=excl+loc[k];
  __syncthreads();
  int* ob=order+(size_t)b*Npts;
  for(int j=tid;j<Npts;j+=256){
    int c=mcode(pb[j*3],pb[j*3+1],pb[j*3+2]);
    int p=atomicAdd(&hist[c],1);
    ob[p]=j;
  }
}

// ----------------------------- FPS v9 (round-14 proven best) -----------------------------
// 8 warps, 4 contiguous Morton subregions/warp; warp-uniform skip via cached
// squared thresholds; FMNMX-only sweep; post-hoc lane-local index scan using
// vloc (overlaps redux_max); float4 spos (LDS.128 coords); 3-level tree slot
// scan; parity slots -> one barrier/iter. Selections bit-exact vs reference.
template<int P>
__global__ void fps9(const float* __restrict__ pos,const int* __restrict__ order,
                     int Npts,int m,float* __restrict__ centers){
  constexpr int SUBP=P/4;
  constexpr int SUBN=8*P;              // 32*SUBP points per subregion
  extern __shared__ float sdyn[];      // [Npts*4] spos(float4) + [m] int wlist
  float* spos=sdyn;
  int* wlist=(int*)(sdyn+(size_t)Npts*4);
  __shared__ unsigned long long slot[2][8];
  int b=blockIdx.x, tid=threadIdx.x, lane=tid&31, w=tid>>5;
  const float* pb=pos+(size_t)b*Npts*3;
  for(int i=tid;i<Npts;i+=256){
    spos[i*4+0]=pb[i*3+0]; spos[i*4+1]=pb[i*3+1]; spos[i*4+2]=pb[i*3+2]; spos[i*4+3]=0.f;
  }
  __syncthreads();
  int region=((w&3)<<1)|(w>>2);
  int wbase=region*(P*32);
  const int* ob=order+(size_t)b*Npts;
  int pid[P]; float mind[P];
  unsigned long long px2[P/2],py2[P/2],pz2[P/2];
  float ctrx[4],ctry[4],ctrz[4],radr[4],submax[4],thr2[4];
#pragma unroll
  for(int r=0;r<4;r++){
    float lx[SUBP],ly[SUBP],lz[SUBP];
    float sx=0.f,sy=0.f,sz=0.f;
#pragma unroll
    for(int e=0;e<SUBP;e++){
      int o=ob[wbase + r*SUBN + lane*SUBP + e];
      int p=r*SUBP+e; pid[p]=o;
      lx[e]=spos[o*4]; ly[e]=spos[o*4+1]; lz[e]=spos[o*4+2];
      sx+=lx[e]; sy+=ly[e]; sz+=lz[e];
      mind[p]=__int_as_float(0x7f800000);
    }
#pragma unroll
    for(int off=16;off;off>>=1){
      sx+=__shfl_down_sync(0xffffffffu,sx,off);
      sy+=__shfl_down_sync(0xffffffffu,sy,off);
      sz+=__shfl_down_sync(0xffffffffu,sz,off);
    }
    float cxr=__shfl_sync(0xffffffffu,sx,0)*(1.f/SUBN);
    float cyr=__shfl_sync(0xffffffffu,sy,0)*(1.f/SUBN);
    float czr=__shfl_sync(0xffffffffu,sz,0)*(1.f/SUBN);
    float md2=0.f;
#pragma unroll
    for(int e=0;e<SUBP;e++){
      float dx=lx[e]-cxr,dy=ly[e]-cyr,dz=lz[e]-czr;
      md2=fmaxf(md2,fmaf(dx,dx,fmaf(dy,dy,dz*dz)));
    }
    md2=__uint_as_float(__reduce_max_sync(0xffffffffu,__float_as_uint(md2)));
    ctrx[r]=cxr; ctry[r]=cyr; ctrz[r]=czr;
    radr[r]=sqrtf(md2)+1e-4f;
    submax[r]=__int_as_float(0x7f800000);
    thr2[r]=__int_as_float(0x7f800000);           // +inf -> first iteration fully active
#pragma unroll
    for(int j=0;j<SUBP/2;j++){
      px2[r*(SUBP/2)+j]=pk2(lx[2*j],lx[2*j+1]);
      py2[r*(SUBP/2)+j]=pk2(ly[2*j],ly[2*j+1]);
      pz2[r*(SUBP/2)+j]=pk2(lz[2*j],lz[2*j+1]);
    }
  }
  float cx=spos[0],cy=spos[1],cz=spos[2];
  unsigned wvmax=0x7f800000u;          // cached warp max (bits)
  int wimin=0;
  if(tid==0) wlist[0]=0;
  for(int i=1;i<m;i++){
    bool act[4]; bool any=false;
#pragma unroll
    for(int r=0;r<4;r++){
      float dgx=cx-ctrx[r],dgy=cy-ctry[r],dgz=cz-ctrz[r];
      float d2g=fmaf(dgx,dgx,fmaf(dgy,dgy,dgz*dgz));
      act[r]=(d2g<thr2[r]);
      any|=act[r];
    }
    if(any){                                      // warp-uniform (sphere data lane-identical)
      unsigned long long ncx=pk2(-cx,-cx),ncy=pk2(-cy,-cy),ncz=pk2(-cz,-cz);
#pragma unroll
      for(int r=0;r<4;r++) if(act[r]){
        float mr=-1.f;
#pragma unroll
        for(int j=0;j<SUBP/2;j++){
          int p2=r*(SUBP/2)+j, p=r*SUBP+2*j;
          unsigned long long dx=addx2(px2[p2],ncx);
          unsigned long long dy=addx2(py2[p2],ncy);
          unsigned long long dz=addx2(pz2[p2],ncz);
          unsigned long long sx=mulx2(dx,dx);
          unsigned long long sy=mulx2(dy,dy);
          unsigned long long sz=mulx2(dz,dz);
          unsigned long long d2=addx2(addx2(sx,sy),sz);
          float dlo,dhi; upk2(d2,dlo,dhi);
          float m0=fminf(mind[p],dlo);   mind[p]=m0;   mr=fmaxf(mr,m0);
          float m1=fminf(mind[p+1],dhi); mind[p+1]=m1; mr=fmaxf(mr,m1);
        }
        submax[r]=mr;
      }
      float vloc=fmaxf(fmaxf(submax[0],submax[1]),fmaxf(submax[2],submax[3]));
      // lane-local index scan (independent of redux_max -> overlaps its latency)
      int cpid=0x7fffffff;
#pragma unroll
      for(int p=0;p<P;p++)
        if(mind[p]==vloc) cpid=min(cpid,pid[p]);
      unsigned fb=__float_as_uint(vloc);
      unsigned vm=__reduce_max_sync(0xffffffffu,fb);
      unsigned cand=(fb==vm)? (unsigned)cpid : 0xffffffffu;
      unsigned im=__reduce_min_sync(0xffffffffu,cand);
      wvmax=vm; wimin=(int)im;
      float sth=sqrtf(__uint_as_float(vm));
#pragma unroll
      for(int r=0;r<4;r++){ float t=radr[r]+1e-3f+sth; thr2[r]=t*t; }
    }
    int par=i&1;
    if(lane==0) slot[par][w]=((unsigned long long)wvmax<<32)|(unsigned)(~wimin);
    __syncthreads();
    unsigned long long s0=slot[par][0],s1=slot[par][1],s2=slot[par][2],s3=slot[par][3];
    unsigned long long s4=slot[par][4],s5=slot[par][5],s6=slot[par][6],s7=slot[par][7];
    s0=umax64(s0,s1); s2=umax64(s2,s3); s4=umax64(s4,s5); s6=umax64(s6,s7);
    s0=umax64(s0,s2); s4=umax64(s4,s6);
    unsigned long long best=umax64(s0,s4);
    int wpid=(int)(~((unsigned)best));
    if(tid==0) wlist[i]=wpid;
    float4 wc=*(const float4*)(spos+(size_t)wpid*4);
    cx=wc.x; cy=wc.y; cz=wc.z;
  }
  __syncthreads();
  float* dst=centers+(size_t)b*m*3;
  for(int i=tid;i<m;i+=256){
    int p=wlist[i];
    dst[i*3]=spos[p*4]; dst[i*3+1]=spos[p*4+1]; dst[i*3+2]=spos[p*4+2];
  }
}

// ------------------- radius neighbors, 8 centers/block, packed f32x2 -------------------
__global__ void nbr8(const float* __restrict__ pos,int Npts,
                     const float* __restrict__ cen,int m,float r2,int cidx,
                     int* __restrict__ rowC,int* __restrict__ rowN,
                     int* __restrict__ cbase,int* __restrict__ ccnt){
  __shared__ float cd[8][CPC]; __shared__ int ci[8][CPC];
  __shared__ int scnt[8];
  __shared__ float cc[24];
  int b=blockIdx.y, tid=threadIdx.x, lane=tid&31, w=tid>>5;
  int c0=blockIdx.x*8;
  if(tid<8) scnt[tid]=0;
  if(tid<24) cc[tid]=cen[((size_t)(b*m+c0))*3+tid];
  __syncthreads();
  unsigned long long pcx[4],pcy[4],pcz[4];
#pragma unroll
  for(int kp=0;kp<4;kp++){
    pcx[kp]=pk2(cc[(2*kp)*3],  cc[(2*kp+1)*3]);
    pcy[kp]=pk2(cc[(2*kp)*3+1],cc[(2*kp+1)*3+1]);
    pcz[kp]=pk2(cc[(2*kp)*3+2],cc[(2*kp+1)*3+2]);
  }
  const float* pb=pos+(size_t)b*Npts*3;
  for(int j=tid;j<Npts;j+=256){
    float x=pb[j*3],y=pb[j*3+1],z=pb[j*3+2];
    unsigned long long nx=pk2(-x,-x),ny=pk2(-y,-y),nz=pk2(-z,-z);
#pragma unroll
    for(int kp=0;kp<4;kp++){
      unsigned long long dx=addx2(pcx[kp],nx);
      unsigned long long dy=addx2(pcy[kp],ny);
      unsigned long long dz=addx2(pcz[kp],nz);
      unsigned long long sx=mulx2(dx,dx);
      unsigned long long sy=mulx2(dy,dy);
      unsigned long long sz=mulx2(dz,dz);
      unsigned long long d2=addx2(addx2(sx,sy),sz);
      float d0,d1; upk2(d2,d0,d1);
      if(d0<=r2){
        int p=atomicAdd(&scnt[2*kp],1);
        if(p<CPC){ cd[2*kp][p]=d0; ci[2*kp][p]=j; }
      }
      if(d1<=r2){
        int p=atomicAdd(&scnt[2*kp+1],1);
        if(p<CPC){ cd[2*kp+1][p]=d1; ci[2*kp+1][p]=j; }
      }
    }
  }
  __syncthreads();
  int gc=b*m+c0+w;
  int n=scnt[w];
  int cnt=min(n,KNB);
  int basev=0;
  if(lane==0) basev=atomicAdd(&g_rowcnt[cidx],cnt);
  basev=__shfl_sync(0xffffffffu,basev,0);
  if(lane==0){ cbase[gc]=basev; ccnt[gc]=cnt; }
  if(n<=KNB){
    for(int q=lane;q<cnt;q+=32){
      rowC[basev+q]=gc;
      rowN[basev+q]=ci[w][q];
    }
  }else{
    int nn=min(n,CPC);
    for(int s=0;s<KNB;s++){
      float bvv=__int_as_float(0x7f800000); int bid=0x7fffffff; int bp=-1;
      for(int p=lane;p<nn;p+=32){
        float v=cd[w][p]; int id=ci[w][p];
        if(v<bvv||(v==bvv&&id<bid)){bvv=v;bid=id;bp=p;}
      }
#pragma unroll
      for(int off=16;off;off>>=1){
        float ov=__shfl_down_sync(0xffffffffu,bvv,off);
        int   oi=__shfl_down_sync(0xffffffffu,bid,off);
        int   op=__shfl_down_sync(0xffffffffu,bp,off);
        if(ov<bvv||(ov==bvv&&oi<bid)){bvv=ov;bid=oi;bp=op;}
      }
      bp=__shfl_sync(0xffffffffu,bp,0);
      if(lane==0){ rowC[basev+s]=gc; rowN[basev+s]=bid; }
      if(lane==0) cd[w][bp]=__int_as_float(0x7f800000);
      __syncwarp();
    }
  }
}

// ------------------- SA0 layer1: rel(3) -> 64, relu -------------------
__global__ void pass1_sa0(const float* __restrict__ pos,
                          const float* __restrict__ w1,const float* __restrict__ b1){
  __shared__ float sw[3*64]; __shared__ float sb[64];
  int R=g_rowcnt[0];
  if(blockIdx.x*256>=R) return;
  int tid=threadIdx.x;
  if(tid<192) sw[tid]=w1[tid];
  if(tid<64)  sb[tid]=b1[tid];
  __syncthreads();
  int r=blockIdx.x*256+tid;
  if(r>=R) return;
  int gc=g_rowCenter[r], j=g_rowNbr[r];
  int b=gc/NM0;
  const float* pj=pos+((size_t)b*NPTS0+j)*3;
  float r0=pj[0]-g_pos1[gc*3], r1=pj[1]-g_pos1[gc*3+1], r2=pj[2]-g_pos1[gc*3+2];
  float4* out=(float4*)(g_bufA+(size_t)r*64);
#pragma unroll
  for(int q=0;q<16;q++){
    float4 v;
    v.x=fmaxf(fmaf(r0,sw[q*4+0],fmaf(r1,sw[64+q*4+0],fmaf(r2,sw[128+q*4+0],sb[q*4+0]))),0.f);
    v.y=fmaxf(fmaf(r0,sw[q*4+1],fmaf(r1,sw[64+q*4+1],fmaf(r2,sw[128+q*4+1],sb[q*4+1]))),0.f);
    v.z=fmaxf(fmaf(r0,sw[q*4+2],fmaf(r1,sw[64+q*4+2],fmaf(r2,sw[128+q*4+2],sb[q*4+2]))),0.f);
    v.w=fmaxf(fmaf(r0,sw[q*4+3],fmaf(r1,sw[64+q*4+3],fmaf(r2,sw[128+q*4+3],sb[q*4+3]))),0.f);
    out[q]=v;
  }
}

// ------------- fused masked BN stats + fold (last-block pattern) -------------
__global__ void stats_fold(int sel,int C,int Rparam,int cidx,int mode,
                           const float* __restrict__ gma,const float* __restrict__ bet,
                           const float* __restrict__ w2,const float* __restrict__ b2){
  __shared__ float ssm[256], sqm[256];
  __shared__ bool isLast;
  int tid=threadIdx.x;
  int R=(Rparam>=0)? Rparam : g_rowcnt[cidx];
  const float* buf = sel ? g_bufB : g_bufA;
  int t=blockIdx.x*256+tid;
  int ch=t%C;
  int rstep=(gridDim.x*256)/C;
  float s0=0.f,q0=0.f,s1=0.f,q1=0.f;
  int r=t/C;
  for(; r+rstep<R; r+=2*rstep){
    float v0=buf[(size_t)r*C+ch];
    float v1=buf[(size_t)(r+rstep)*C+ch];
    s0+=v0; q0=fmaf(v0,v0,q0);
    s1+=v1; q1=fmaf(v1,v1,q1);
  }
  if(r<R){ float v=buf[(size_t)r*C+ch]; s0+=v; q0=fmaf(v,v,q0); }
  ssm[tid]=s0+s1; sqm[tid]=q0+q1;
  __syncthreads();
  for(int step=128; step>=C; step>>=1){
    if(tid<step){ ssm[tid]+=ssm[tid+step]; sqm[tid]+=sqm[tid+step]; }
    __syncthreads();
  }
  if(tid<C){
    atomicAdd(&g_sum1[tid],(double)ssm[tid]);
    atomicAdd(&g_sq1[tid],(double)sqm[tid]);
  }
  __threadfence();
  __syncthreads();
  if(tid==0) isLast=(atomicAdd(&g_done,1)==(int)gridDim.x-1);
  __syncthreads();
  if(!isLast) return;
  __shared__ float a1[256], c1[256];
  double cnt=(double)R;
  if(tid<C){
    double mu=g_sum1[tid]/cnt;
    double var=g_sq1[tid]/cnt-mu*mu;
    float a=gma[tid]*rsqrtf((float)var+EPSBN);
    a1[tid]=a; c1[tid]=bet[tid]-a*(float)mu;
    g_sum1[tid]=0.0; g_sq1[tid]=0.0;
  }
  __syncthreads();
  if(mode==0){
    for(int i=tid;i<C*128;i+=256) g_w2eff[i]=a1[i>>7]*w2[i];
    if(tid<128){
      float s=b2[tid];
      for(int k=0;k<C;k++) s=fmaf(c1[k],w2[k*128+tid],s);
      g_b2eff[tid]=s;
    }
  }else{
    if(tid<C){ g_a2[tid]=a1[tid]; g_c2[tid]=c1[tid]; }
  }
  if(tid==0) g_done=0;
}

// ------------------- layer2 tiled GEMM -------------------
__global__ void pass2(int C1,int cidx){
  int R=g_rowcnt[cidx];
  int r0=blockIdx.x*64;
  if(r0>=R) return;
  __shared__ __align__(16) float Ws[32*128];
  __shared__ __align__(16) float As[64*32];
  int tid=threadIdx.x;
  int row=tid>>2, cg=tid&3;
  float acc[32];
#pragma unroll
  for(int j=0;j<32;j++) acc[j]=g_b2eff[cg*32+j];
  int nchunks=C1>>5;
  for(int kc=0;kc<nchunks;kc++){
    for(int i=tid;i<4096;i+=256) Ws[i]=g_w2eff[kc*4096+i];
    for(int i=tid;i<2048;i+=256){
      int rr=i>>5, kk=i&31; int rA=r0+rr;
      As[i]=(rA<R)? g_bufA[(size_t)rA*C1+kc*32+kk] : 0.f;
    }
    __syncthreads();
#pragma unroll 8
    for(int kk=0;kk<32;kk++){
      float a=As[row*32+kk];
      const float4* w4=(const float4*)(Ws+kk*128+cg*32);
#pragma unroll
      for(int j=0;j<8;j++){
        float4 w=w4[j];
        acc[j*4+0]=fmaf(a,w.x,acc[j*4+0]);
        acc[j*4+1]=fmaf(a,w.y,acc[j*4+1]);
        acc[j*4+2]=fmaf(a,w.z,acc[j*4+2]);
        acc[j*4+3]=fmaf(a,w.w,acc[j*4+3]);
      }
    }
    __syncthreads();
  }
  int rA=r0+row;
  if(rA<R){
    float* out=g_bufB+(size_t)rA*128+cg*32;
#pragma unroll
    for(int j=0;j<32;j++) out[j]=fmaxf(acc[j],0.f);
  }
}

// ------------------- SA1 layer1 -------------------
__global__ void pass1_sa1(const float* __restrict__ w1,const float* __restrict__ b1){
  int R=g_rowcnt[1];
  int r0=blockIdx.x*64;
  if(r0>=R) return;
  __shared__ __align__(16) float Ws[32*128];
  __shared__ __align__(16) float As[64*32];
  __shared__ int xrow[64]; __shared__ int gcl[64];
  int tid=threadIdx.x;
  if(tid<64){
    int rA=r0+tid;
    int gc=(rA<R)? g_rowCenter1[rA]:0;
    int j =(rA<R)? g_rowNbr1[rA]:0;
    gcl[tid]=gc; xrow[tid]=(gc>>9)*NM0 + j;
  }
  __syncthreads();
  int row=tid>>2, cg=tid&3;
  float acc[32];
#pragma unroll
  for(int j=0;j<32;j++) acc[j]=b1[cg*32+j];
  for(int kc=0;kc<5;kc++){
    for(int i=tid;i<4096;i+=256){
      int kk=i>>7, ch=i&127; int kg=kc*32+kk;
      Ws[i]=(kg<131)? w1[kg*128+ch] : 0.f;
    }
    for(int i=tid;i<2048;i+=256){
      int rr=i>>5, kk=i&31; int rA=r0+rr;
      float v=0.f;
      if(rA<R){
        if(kc<4)       v=g_x1[(size_t)xrow[rr]*128+kc*32+kk];
        else if(kk<3)  v=g_pos1[xrow[rr]*3+kk]-g_pos2[gcl[rr]*3+kk];
      }
      As[i]=v;
    }
    __syncthreads();
#pragma unroll 8
    for(int kk=0;kk<32;kk++){
      float a=As[row*32+kk];
      const float4* w4=(const float4*)(Ws+kk*128+cg*32);
#pragma unroll
      for(int j=0;j<8;j++){
        float4 w=w4[j];
        acc[j*4+0]=fmaf(a,w.x,acc[j*4+0]);
        acc[j*4+1]=fmaf(a,w.y,acc[j*4+1]);
        acc[j*4+2]=fmaf(a,w.z,acc[j*4+2]);
        acc[j*4+3]=fmaf(a,w.w,acc[j*4+3]);
      }
    }
    __syncthreads();
  }
  int rA=r0+row;
  if(rA<R){
    float* out=g_bufA+(size_t)rA*128+cg*32;
#pragma unroll
    for(int j=0;j<32;j++) out[j]=fmaxf(acc[j],0.f);
  }
}

// ------------------- per-center max + BN2 affine -------------------
__global__ void maxfin_sa0(){
  int gc=blockIdx.x, ch=threadIdx.x;
  int base=g_cbase[gc], cnt=g_ccnt[gc];
  float mx=__int_as_float(0xff800000);
  for(int k=0;k<cnt;k++) mx=fmaxf(mx,g_bufB[(size_t)(base+k)*128+ch]);
  g_x1[(size_t)gc*128+ch]=fmaf(g_a2[ch],mx,g_c2[ch]);
}

__global__ void maxfin_sa1(){
  int gc=blockIdx.x, ch=threadIdx.x;
  int base=g_cbase1[gc], cnt=g_ccnt1[gc];
  float mx=__int_as_float(0xff800000);
  for(int k=0;k<cnt;k++) mx=fmaxf(mx,g_bufB[(size_t)(base+k)*128+ch]);
  g_featga[(size_t)gc*131+ch]=fmaf(g_a2[ch],mx,g_c2[ch]);
  if(ch<3) g_featga[(size_t)gc*131+128+ch]=g_pos2[gc*3+ch];
}

// ------------------- global MLP -------------------
__global__ void ga_pass(const float* __restrict__ w,const float* __restrict__ bias){
  __shared__ __align__(16) float Ws[32*256];
  __shared__ __align__(16) float As[32*32];
  int tid=threadIdx.x;
  int r0=blockIdx.x*32;
  int row=tid>>3, cg=tid&7; int ch0=cg*32;
  float acc[32];
#pragma unroll
  for(int j=0;j<32;j++) acc[j]=bias[ch0+j];
  for(int kc=0;kc<5;kc++){
    for(int i=tid;i<8192;i+=256){
      int kk=i>>8, ch=i&255; int kg=kc*32+kk;
      Ws[i]=(kg<131)? w[kg*256+ch] : 0.f;
    }
    for(int i=tid;i<1024;i+=256){
      int rr=i>>5, kk=i&31; int kg=kc*32+kk;
      As[i]=(kg<131)? g_featga[(size_t)(r0+rr)*131+kg] : 0.f;
    }
    __syncthreads();
#pragma unroll 8
    for(int kk=0;kk<32;kk++){
      float a=As[row*32+kk];
      const float4* w4=(const float4*)(Ws+kk*256+ch0);
#pragma unroll
      for(int j=0;j<8;j++){
        float4 wv=w4[j];
        acc[j*4+0]=fmaf(a,wv.x,acc[j*4+0]);
        acc[j*4+1]=fmaf(a,wv.y,acc[j*4+1]);
        acc[j*4+2]=fmaf(a,wv.z,acc[j*4+2]);
        acc[j*4+3]=fmaf(a,wv.w,acc[j*4+3]);
      }
    }
    __syncthreads();
  }
  float* out=g_bufB+(size_t)(r0+row)*256+ch0;
#pragma unroll
  for(int j=0;j<32;j++) out[j]=fmaxf(acc[j],0.f);
}

// ------------------- global max + BN + FC head -------------------
__global__ void final_kernel(const float* __restrict__ l0w,const float* __restrict__ l0b,
                             const float* __restrict__ l1w,const float* __restrict__ l1b,
                             float* __restrict__ out){
  __shared__ float sy[256], sz[256];
  int b=blockIdx.x, ch=threadIdx.x;
  const float* bb=g_bufB+(size_t)b*512*256;
  float m0=__int_as_float(0xff800000), m1=m0, m2=m0, m3=m0;
  for(int r=0;r<512;r+=4){
    m0=fmaxf(m0,bb[(r+0)*256+ch]);
    m1=fmaxf(m1,bb[(r+1)*256+ch]);
    m2=fmaxf(m2,bb[(r+2)*256+ch]);
    m3=fmaxf(m3,bb[(r+3)*256+ch]);
  }
  float mx=fmaxf(fmaxf(m0,m1),fmaxf(m2,m3));
  sy[ch]=fmaxf(fmaf(g_a2[ch],mx,g_c2[ch]),0.f);
  __syncthreads();
  float s=l0b[ch];
  for(int k=0;k<256;k++) s=fmaf(sy[k],l0w[k*256+ch],s);
  sz[ch]=fmaxf(s,0.f);
  __syncthreads();
  if(ch<10){
    float o=l1b[ch];
    for(int k=0;k<256;k++) o=fmaf(sz[k],l1w[k*10+ch],o);
    out[b*10+ch]=o;
  }
}

// ----------------------------- host launch -----------------------------
extern "C" void kernel_launch(void* const* d_in, const int* in_sizes, int n_in,
                              void* d_out, int out_size){
  const float* pos    =(const float*)d_in[0];
  const float* sa0_w1 =(const float*)d_in[1];
  const float* sa0_b1 =(const float*)d_in[2];
  const float* sa0_g1 =(const float*)d_in[3];
  const float* sa0_be1=(const float*)d_in[4];
  const float* sa0_w2 =(const float*)d_in[5];
  const float* sa0_b2 =(const float*)d_in[6];
  const float* sa0_g2 =(const float*)d_in[7];
  const float* sa0_be2=(const float*)d_in[8];
  const float* sa1_w1 =(const float*)d_in[9];
  const float* sa1_b1 =(const float*)d_in[10];
  const float* sa1_g1 =(const float*)d_in[11];
  const float* sa1_be1=(const float*)d_in[12];
  const float* sa1_w2 =(const float*)d_in[13];
  const float* sa1_b2 =(const float*)d_in[14];
  const float* sa1_g2 =(const float*)d_in[15];
  const float* sa1_be2=(const float*)d_in[16];
  const float* ga_w   =(const float*)d_in[17];
  const float* ga_b   =(const float*)d_in[18];
  const float* ga_g   =(const float*)d_in[19];
  const float* ga_be  =(const float*)d_in[20];
  const float* l0_w   =(const float*)d_in[21];
  const float* l0_b   =(const float*)d_in[22];
  const float* l1_w   =(const float*)d_in[23];
  const float* l1_b   =(const float*)d_in[24];
  float* out=(float*)d_out;

  void *p_pos1,*p_pos2,*p_ord0,*p_ord1;
  void *p_rc0,*p_rn0,*p_cb0,*p_cc0,*p_rc1,*p_rn1,*p_cb1,*p_cc1;
  cudaGetSymbolAddress(&p_pos1,g_pos1);
  cudaGetSymbolAddress(&p_pos2,g_pos2);
  cudaGetSymbolAddress(&p_ord0,g_ord0);
  cudaGetSymbolAddress(&p_ord1,g_ord1);
  cudaGetSymbolAddress(&p_rc0,g_rowCenter);
  cudaGetSymbolAddress(&p_rn0,g_rowNbr);
  cudaGetSymbolAddress(&p_cb0,g_cbase);
  cudaGetSymbolAddress(&p_cc0,g_ccnt);
  cudaGetSymbolAddress(&p_rc1,g_rowCenter1);
  cudaGetSymbolAddress(&p_rn1,g_rowNbr1);
  cudaGetSymbolAddress(&p_cb1,g_cbase1);
  cudaGetSymbolAddress(&p_cc1,g_ccnt1);

  static cudaStream_t s1=nullptr;
  static cudaEvent_t e0=nullptr,e1=nullptr;
  if(!s1){
    cudaStreamCreateWithFlags(&s1,cudaStreamNonBlocking);
    cudaEventCreateWithFlags(&e0,cudaEventDisableTiming);
    cudaEventCreateWithFlags(&e1,cudaEventDisableTiming);
  }

  const int SM0=(NPTS0*4+NM0)*(int)sizeof(float);   // 73728 B
  const int SM1=(NM0*4+NM1)*(int)sizeof(float);     // 34816 B
  cudaFuncSetAttribute(fps9<16>,cudaFuncAttributeMaxDynamicSharedMemorySize,SM0);
  cudaFuncSetAttribute(fps9<8>, cudaFuncAttributeMaxDynamicSharedMemorySize,SM1);

  const float R2_0=(float)(0.2*0.2);
  const float R2_1=(float)(0.4*0.4);

  // ---------------- SA0 geometry (stream 0) ----------------
  sortpts<<<NB,256>>>(pos,NPTS0,(int*)p_ord0,0);
  fps9<16><<<NB,256,SM0>>>(pos,(const int*)p_ord0,NPTS0,NM0,(float*)p_pos1);
  cudaEventRecord(e0,0);

  // ---------------- SA1 geometry (stream s1, depends only on pos1) ----------------
  cudaStreamWaitEvent(s1,e0,0);
  sortpts<<<NB,256,0,s1>>>((const float*)p_pos1,NM0,(int*)p_ord1,1);
  fps9<8><<<NB,256,SM1,s1>>>((const float*)p_pos1,(const int*)p_ord1,NM0,NM1,(float*)p_pos2);
  { dim3 g(NM1/8,NB);
    nbr8<<<g,256,0,s1>>>((const float*)p_pos1,NM0,(const float*)p_pos2,NM1,R2_1,1,
                         (int*)p_rc1,(int*)p_rn1,(int*)p_cb1,(int*)p_cc1); }
  cudaEventRecord(e1,s1);

  // ---------------- SA0 MLP chain (stream 0, concurrent with s1) ----------------
  { dim3 g(NM0/8,NB);
    nbr8<<<g,256>>>(pos,NPTS0,(const float*)p_pos1,NM0,R2_0,0,
                    (int*)p_rc0,(int*)p_rn0,(int*)p_cb0,(int*)p_cc0); }
  pass1_sa0<<<R0MAX/256,256>>>(pos,sa0_w1,sa0_b1);
  stats_fold<<<256,256>>>(0,64,-1,0,0,sa0_g1,sa0_be1,sa0_w2,sa0_b2);
  pass2<<<R0MAX/64,256>>>(64,0);
  stats_fold<<<256,256>>>(1,128,-1,0,1,sa0_g2,sa0_be2,nullptr,nullptr);
  maxfin_sa0<<<NB*NM0,128>>>();

  // ---------------- join, SA1 MLP chain ----------------
  cudaStreamWaitEvent(0,e1,0);
  pass1_sa1<<<R1MAX/64,256>>>(sa1_w1,sa1_b1);
  stats_fold<<<256,256>>>(0,128,-1,1,0,sa1_g1,sa1_be1,sa1_w2,sa1_b2);
  pass2<<<R1MAX/64,256>>>(128,1);
  stats_fold<<<256,256>>>(1,128,-1,1,1,sa1_g2,sa1_be2,nullptr,nullptr);
  maxfin_sa1<<<NB*NM1,128>>>();

  // ---------------- global MLP + head ----------------
  ga_pass<<<(NB*NM1)/32,256>>>(ga_w,ga_b);
  stats_fold<<<256,256>>>(1,256,NB*NM1,0,1,ga_g,ga_be,nullptr,nullptr);
  final_kernel<<<NB,256>>>(l0_w,l0_b,l1_w,l1_b,out);
}